// round 5
// baseline (speedup 1.0000x reference)
#include <cuda_runtime.h>
#include <cuda_bf16.h>
#include <cstdint>
#include <math.h>

#define Bz 2
#define Sz 2048
#define Dz 1024
#define Hz 16
#define DHz 64
#define NROW (Bz*Sz)   // 4096

// ---------------- device scratch (no allocations allowed) -------------------
__device__ float g_q[Bz*Hz*Sz*DHz];       // [B,H,S,DH]
__device__ float g_k[Bz*Hz*Sz*DHz];       // [B,H,S,DH]
__device__ float g_vt[Bz*Hz*DHz*Sz];      // [B,H,DH,S]  (transposed V)
__device__ float g_attn[Bz*Sz*Dz];        // merged heads [B,S,D]
__device__ float g_inv[Bz*Hz*Sz];         // 1/rowsum of exp

// ---------------- helpers ---------------------------------------------------
__device__ __forceinline__ uint32_t packbf(float a, float b){
    __nv_bfloat162 t = __floats2bfloat162_rn(a, b);
    return *reinterpret_cast<uint32_t*>(&t);
}

__device__ __forceinline__ void split4(float4 x, uint32_t& h0, uint32_t& h1,
                                       uint32_t& l0, uint32_t& l1){
    float hx = __bfloat162float(__float2bfloat16(x.x));
    float hy = __bfloat162float(__float2bfloat16(x.y));
    float hz = __bfloat162float(__float2bfloat16(x.z));
    float hw = __bfloat162float(__float2bfloat16(x.w));
    h0 = packbf(hx, hy);
    h1 = packbf(hz, hw);
    l0 = packbf(x.x - hx, x.y - hy);
    l1 = packbf(x.z - hz, x.w - hw);
}

__device__ __forceinline__ void mma16816(float* d, const uint32_t* a, const uint32_t* b){
    asm volatile("mma.sync.aligned.m16n8k16.row.col.f32.bf16.bf16.f32 "
        "{%0,%1,%2,%3}, {%4,%5,%6,%7}, {%8,%9}, {%0,%1,%2,%3};"
        : "+f"(d[0]), "+f"(d[1]), "+f"(d[2]), "+f"(d[3])
        : "r"(a[0]), "r"(a[1]), "r"(a[2]), "r"(a[3]), "r"(b[0]), "r"(b[1]));
}

// ---------------- generic GEMM mainloop (NT) for proj/dense ----------------
template<int BN>
__device__ __forceinline__ void gemm_bf16(
    const float* __restrict__ A, int lda,
    const float* __restrict__ B, int ldb, int K,
    uint32_t* sm, float acc[4][BN/32][4], int tid)
{
    constexpr int N_AT = BN/32;
    constexpr int AW = 20;
    constexpr int ATw = 128*AW;
    constexpr int BTw = BN*AW;
    constexpr int STG = 2*ATw + 2*BTw;
    const int wid = tid>>5, lane = tid&31;
    const int wm = (wid>>2)*64;
    const int wn = (wid&3)*(BN/4);
    const int gid = lane>>2, qid = lane&3;
    const int NC = K/32;

    float4 pa[4];
    float4 pb[N_AT];

    auto ldga = [&](int c){
#pragma unroll
        for (int i=0;i<4;i++){
            int f = i*256+tid, row = f>>3, c4 = f&7;
            pa[i] = *(const float4*)(A + (size_t)row*lda + c*32 + c4*4);
        }
#pragma unroll
        for (int i=0;i<N_AT;i++){
            int f = i*256+tid, row = f>>3, c4 = f&7;
            pb[i] = *(const float4*)(B + (size_t)row*ldb + c*32 + c4*4);
        }
    };
    auto sts = [&](int s){
        uint32_t* Ah = sm + s*STG;
        uint32_t* Al = Ah + ATw;
        uint32_t* Bh = Al + ATw;
        uint32_t* Bl = Bh + BTw;
#pragma unroll
        for (int i=0;i<4;i++){
            int f = i*256+tid, row = f>>3, c4 = f&7;
            uint32_t h0,h1,l0,l1; split4(pa[i],h0,h1,l0,l1);
            Ah[row*AW + c4*2]   = h0; Ah[row*AW + c4*2+1] = h1;
            Al[row*AW + c4*2]   = l0; Al[row*AW + c4*2+1] = l1;
        }
#pragma unroll
        for (int i=0;i<N_AT;i++){
            int f = i*256+tid, row = f>>3, c4 = f&7;
            uint32_t h0,h1,l0,l1; split4(pb[i],h0,h1,l0,l1);
            Bh[row*AW + c4*2]   = h0; Bh[row*AW + c4*2+1] = h1;
            Bl[row*AW + c4*2]   = l0; Bl[row*AW + c4*2+1] = l1;
        }
    };

    ldga(0); sts(0); __syncthreads();

    for (int c = 0; c < NC; c++){
        int cur = c & 1;
        if (c+1 < NC) ldga(c+1);

        const uint32_t* Ah = sm + cur*STG;
        const uint32_t* Al = Ah + ATw;
        const uint32_t* Bh = Al + ATw;
        const uint32_t* Bl = Bh + BTw;
#pragma unroll
        for (int c16 = 0; c16 < 2; c16++){
            uint32_t aH[4][4], aL[4][4];
            const int w0 = c16*8 + qid;
#pragma unroll
            for (int mi=0;mi<4;mi++){
                int r0 = wm + mi*16 + gid;
                aH[mi][0]=Ah[r0*AW+w0];    aH[mi][1]=Ah[(r0+8)*AW+w0];
                aH[mi][2]=Ah[r0*AW+w0+4];  aH[mi][3]=Ah[(r0+8)*AW+w0+4];
                aL[mi][0]=Al[r0*AW+w0];    aL[mi][1]=Al[(r0+8)*AW+w0];
                aL[mi][2]=Al[r0*AW+w0+4];  aL[mi][3]=Al[(r0+8)*AW+w0+4];
            }
            uint32_t bH[N_AT][2], bL[N_AT][2];
#pragma unroll
            for (int ni=0;ni<N_AT;ni++){
                int rn = wn + ni*8 + gid;
                bH[ni][0]=Bh[rn*AW+w0]; bH[ni][1]=Bh[rn*AW+w0+4];
                bL[ni][0]=Bl[rn*AW+w0]; bL[ni][1]=Bl[rn*AW+w0+4];
            }
#pragma unroll
            for (int mi=0;mi<4;mi++)
#pragma unroll
                for (int ni=0;ni<N_AT;ni++){
                    mma16816(acc[mi][ni], aH[mi], bH[ni]);
                    mma16816(acc[mi][ni], aH[mi], bL[ni]);
                    mma16816(acc[mi][ni], aL[mi], bH[ni]);
                }
        }
        __syncthreads();
        if (c+1 < NC){ sts((c+1)&1); __syncthreads(); }
    }
}

template<int BN>
__device__ __forceinline__ void stage_acc(float* stg, float acc[4][BN/32][4],
                                          int tid, float scale, const float* bias_s)
{
    constexpr int SW = BN + 4;
    const int wid = tid>>5, lane = tid&31;
    const int wm = (wid>>2)*64, wn = (wid&3)*(BN/4);
    const int gid = lane>>2, qid = lane&3;
#pragma unroll
    for (int mi=0;mi<4;mi++)
#pragma unroll
        for (int ni=0;ni<BN/32;ni++){
            int r = wm + mi*16 + gid;
            int cc = wn + ni*8 + qid*2;
            float b0 = bias_s ? bias_s[cc]   : 0.f;
            float b1 = bias_s ? bias_s[cc+1] : 0.f;
            stg[(size_t)r*SW + cc]       = acc[mi][ni][0]*scale + b0;
            stg[(size_t)r*SW + cc+1]     = acc[mi][ni][1]*scale + b1;
            stg[(size_t)(r+8)*SW + cc]   = acc[mi][ni][2]*scale + b0;
            stg[(size_t)(r+8)*SW + cc+1] = acc[mi][ni][3]*scale + b1;
        }
}

#define ZERO_ACC(a, NAT) \
    _Pragma("unroll") for (int _i=0;_i<4;_i++) \
    _Pragma("unroll") for (int _j=0;_j<NAT;_j++) \
    _Pragma("unroll") for (int _k=0;_k<4;_k++) a[_i][_j][_k] = 0.f;

// ---------------- merged projections: Y = X @ W^T + b (z selects q/k/v) ----
__global__ __launch_bounds__(256)
void proj_tc(const float* __restrict__ Xq, const float* __restrict__ Xk,
             const float* __restrict__ Xv,
             const float* __restrict__ Wq, const float* __restrict__ bq,
             const float* __restrict__ Wk, const float* __restrict__ bk,
             const float* __restrict__ Wv, const float* __restrict__ bv)
{
    extern __shared__ uint32_t sm[];
    __shared__ float bias_s[128];
    const int tid = threadIdx.x;
    const int which = blockIdx.z;
    const int bn = blockIdx.x*128, bm = blockIdx.y*128;

    const float* X  = (which==0) ? Xq : (which==1) ? Xk : Xv;
    const float* Wm = (which==0) ? Wq : (which==1) ? Wk : Wv;
    const float* bias = (which==0) ? bq : (which==1) ? bk : bv;
    if (tid < 128) bias_s[tid] = bias[bn + tid];

    float acc[4][4][4]; ZERO_ACC(acc, 4);
    gemm_bf16<128>(X + (size_t)bm*Dz, Dz, Wm + (size_t)bn*Dz, Dz, Dz, sm, acc, tid);

    float* stg = (float*)sm;
    stage_acc<128>(stg, acc, tid, 1.f, bias_s);
    __syncthreads();

    if (which == 2){
        for (int i=0;i<64;i++){
            int idx = i*256 + tid;
            int r = idx & 127, c = idx >> 7;
            float v = stg[(size_t)r*132 + c];
            int m = bm + r, b = m>>11, s = m & 2047;
            int col = bn + c, h = col>>6, dh = col&63;
            g_vt[(((size_t)b*Hz + h)*DHz + dh)*Sz + s] = v;
        }
    } else {
        float* dst = which ? g_k : g_q;
        for (int i=0;i<16;i++){
            int f = i*256 + tid, r = f>>5, c4 = f&31;
            float4 v = *(float4*)&stg[(size_t)r*132 + c4*4];
            int m = bm + r, b = m>>11, s = m & 2047;
            int col = bn + c4*4, h = col>>6, dh = col&63;
            *(float4*)&dst[(((size_t)b*Hz + h)*Sz + s)*DHz + dh] = v;
        }
    }
}

// ---------------- fused attention: scores+mask+exp+rowsum+AV ---------------
// grid (16 row-tiles, 32 bh); 256 threads; warp w owns rows [w*16, w*16+16).
// smem word offsets
#define F_QH 0
#define F_QL 4608
#define F_KH 9216
#define F_KL 13824
#define F_VH 18432
#define F_VL 22784
#define F_STG 27136
#define F_SMEM_BYTES 176128

__global__ __launch_bounds__(256)
void attn_fused(const int* __restrict__ mask, float* __restrict__ Wout)
{
    extern __shared__ uint32_t sm[];
    const int tid = threadIdx.x, lane = tid&31, wid = tid>>5;
    const int gid = lane>>2, qid = lane&3;
    const int bh = blockIdx.y, b = bh>>4, h = bh&15;
    const int bm = blockIdx.x*128;
    const int wr = wid*16;

    // load+split Q (persistent)
    {
        const float* Qg = g_q + ((size_t)bh*Sz + bm)*DHz;
#pragma unroll
        for (int i=0;i<8;i++){
            int f = i*256+tid, row = f>>4, c4 = f&15;
            float4 x = *(const float4*)(Qg + (size_t)row*DHz + c4*4);
            uint32_t h0,h1,l0,l1; split4(x,h0,h1,l0,l1);
            sm[F_QH + row*36 + c4*2]   = h0; sm[F_QH + row*36 + c4*2+1] = h1;
            sm[F_QL + row*36 + c4*2]   = l0; sm[F_QL + row*36 + c4*2+1] = l1;
        }
    }

    float O[8][4];
#pragma unroll
    for (int i=0;i<8;i++){ O[i][0]=0.f; O[i][1]=0.f; O[i][2]=0.f; O[i][3]=0.f; }
    float s0 = 0.f, s1 = 0.f;
    uint32_t* stg = sm + F_STG + wid*2112;   // 16 x 132 words per warp

    for (int j = 0; j < 16; j++){
        __syncthreads();
        const int bn = j*128;
        // K tile [128 x 64]
        {
            const float* Kg = g_k + ((size_t)bh*Sz + bn)*DHz;
#pragma unroll
            for (int i=0;i<8;i++){
                int f = i*256+tid, row = f>>4, c4 = f&15;
                float4 x = *(const float4*)(Kg + (size_t)row*DHz + c4*4);
                uint32_t h0,h1,l0,l1; split4(x,h0,h1,l0,l1);
                sm[F_KH + row*36 + c4*2]   = h0; sm[F_KH + row*36 + c4*2+1] = h1;
                sm[F_KL + row*36 + c4*2]   = l0; sm[F_KL + row*36 + c4*2+1] = l1;
            }
        }
        // Vt tile [64 x 128]
        {
            const float* Vg = g_vt + (size_t)bh*DHz*Sz + bn;
#pragma unroll
            for (int i=0;i<8;i++){
                int f = i*256+tid, row = f>>5, c4 = f&31;
                float4 x = *(const float4*)(Vg + (size_t)row*Sz + c4*4);
                uint32_t h0,h1,l0,l1; split4(x,h0,h1,l0,l1);
                sm[F_VH + row*68 + c4*2]   = h0; sm[F_VH + row*68 + c4*2+1] = h1;
                sm[F_VL + row*68 + c4*2]   = l0; sm[F_VL + row*68 + c4*2+1] = l1;
            }
        }
        // mask slice (warp-private): 16 rows x 128 ints
        {
            const int* Mg = mask + ((size_t)b*Sz + bm + wr)*Sz + bn;
#pragma unroll
            for (int i=0;i<16;i++){
                int f = i*32+lane, row = f>>5, c4 = f&31;
                int4 mv = *(const int4*)(Mg + (size_t)row*Sz + c4*4);
                *(int4*)(stg + row*132 + c4*4) = mv;
            }
        }
        __syncthreads();

        // ----- scores MMA: e = Q @ K^T (3-term split) -----
        float e4[16][4];
#pragma unroll
        for (int ni=0;ni<16;ni++){ e4[ni][0]=0.f; e4[ni][1]=0.f; e4[ni][2]=0.f; e4[ni][3]=0.f; }
#pragma unroll
        for (int c16=0;c16<4;c16++){
            const int w0 = c16*8 + qid;
            uint32_t aH[4], aL[4];
            const int r0 = wr + gid;
            aH[0]=sm[F_QH + r0*36 + w0];     aH[1]=sm[F_QH + (r0+8)*36 + w0];
            aH[2]=sm[F_QH + r0*36 + w0+4];   aH[3]=sm[F_QH + (r0+8)*36 + w0+4];
            aL[0]=sm[F_QL + r0*36 + w0];     aL[1]=sm[F_QL + (r0+8)*36 + w0];
            aL[2]=sm[F_QL + r0*36 + w0+4];   aL[3]=sm[F_QL + (r0+8)*36 + w0+4];
#pragma unroll
            for (int ni=0;ni<16;ni++){
                const int rn = ni*8 + gid;
                uint32_t bH[2], bL[2];
                bH[0]=sm[F_KH + rn*36 + w0]; bH[1]=sm[F_KH + rn*36 + w0+4];
                bL[0]=sm[F_KL + rn*36 + w0]; bL[1]=sm[F_KL + rn*36 + w0+4];
                mma16816(e4[ni], aH, bH);
                mma16816(e4[ni], aH, bL);
                mma16816(e4[ni], aL, bH);
            }
        }

        // ----- mask + exp + rowsum + pack -----
        uint32_t Ahi[8][4], Alo[8][4];
#pragma unroll
        for (int ni=0;ni<16;ni++){
            int2 m01 = *(const int2*)(stg + gid*132 + ni*8 + 2*qid);
            int2 m23 = *(const int2*)(stg + (gid+8)*132 + ni*8 + 2*qid);
            float v0 = m01.x ? __expf(e4[ni][0]*0.125f) : 0.f;
            float v1 = m01.y ? __expf(e4[ni][1]*0.125f) : 0.f;
            float v2 = m23.x ? __expf(e4[ni][2]*0.125f) : 0.f;
            float v3 = m23.y ? __expf(e4[ni][3]*0.125f) : 0.f;
            s0 += v0 + v1;  s1 += v2 + v3;
            e4[ni][0]=v0; e4[ni][1]=v1; e4[ni][2]=v2; e4[ni][3]=v3;
            float h0 = __bfloat162float(__float2bfloat16(v0));
            float h1 = __bfloat162float(__float2bfloat16(v1));
            float h2 = __bfloat162float(__float2bfloat16(v2));
            float h3 = __bfloat162float(__float2bfloat16(v3));
            int kc = ni>>1, hl = (ni&1)*2;
            Ahi[kc][hl]   = packbf(h0, h1);
            Ahi[kc][hl+1] = packbf(h2, h3);
            Alo[kc][hl]   = packbf(v0-h0, v1-h1);
            Alo[kc][hl+1] = packbf(v2-h2, v3-h3);
        }
        __syncwarp();
        // stage e (fp32) into warp slice, then coalesced write
#pragma unroll
        for (int ni=0;ni<16;ni++){
            float2 a = make_float2(e4[ni][0], e4[ni][1]);
            float2 c = make_float2(e4[ni][2], e4[ni][3]);
            *(float2*)(stg + gid*132 + ni*8 + 2*qid)     = a;
            *(float2*)(stg + (gid+8)*132 + ni*8 + 2*qid) = c;
        }
        __syncwarp();
        {
            float* Wrow = Wout + ((size_t)bh*Sz + bm + wr)*Sz + bn;
#pragma unroll
            for (int i=0;i<16;i++){
                float4 v = *(float4*)(stg + i*132 + lane*4);
                *(float4*)(Wrow + (size_t)i*Sz + lane*4) = v;
            }
        }

        // ----- AV MMA: O += e @ V (3-term: hi*hi + hi*lo + lo*hi) -----
#pragma unroll
        for (int kc=0;kc<8;kc++){
            const int w0 = kc*8 + qid;
#pragma unroll
            for (int nf=0;nf<8;nf++){
                const int rn = nf*8 + gid;
                uint32_t bH[2], bL[2];
                bH[0]=sm[F_VH + rn*68 + w0]; bH[1]=sm[F_VH + rn*68 + w0+4];
                bL[0]=sm[F_VL + rn*68 + w0]; bL[1]=sm[F_VL + rn*68 + w0+4];
                mma16816(O[nf], Ahi[kc], bH);
                mma16816(O[nf], Ahi[kc], bL);
                mma16816(O[nf], Alo[kc], bH);
            }
        }
    }

    // rowsums -> inverse
    s0 += __shfl_xor_sync(0xffffffffu, s0, 1);
    s0 += __shfl_xor_sync(0xffffffffu, s0, 2);
    s1 += __shfl_xor_sync(0xffffffffu, s1, 1);
    s1 += __shfl_xor_sync(0xffffffffu, s1, 2);
    const float inv0 = 1.0f / s0, inv1 = 1.0f / s1;
    if (qid == 0){
        g_inv[(size_t)bh*Sz + bm + wr + gid]     = inv0;
        g_inv[(size_t)bh*Sz + bm + wr + gid + 8] = inv1;
    }

    // normalized O -> g_attn (stage for coalescing)
    __syncwarp();
#pragma unroll
    for (int nf=0;nf<8;nf++){
        float2 a = make_float2(O[nf][0]*inv0, O[nf][1]*inv0);
        float2 c = make_float2(O[nf][2]*inv1, O[nf][3]*inv1);
        *(float2*)(stg + gid*132 + nf*8 + 2*qid)     = a;
        *(float2*)(stg + (gid+8)*132 + nf*8 + 2*qid) = c;
    }
    __syncwarp();
#pragma unroll
    for (int i=0;i<8;i++){
        int f = i*32 + lane, row = f>>4, c4 = f&15;
        float4 v = *(float4*)(stg + row*132 + c4*4);
        *(float4*)&g_attn[((size_t)b*Sz + bm + wr + row)*Dz + h*DHz + c4*4] = v;
    }
}

// ---------------- normalize weights: w *= inv[row] -------------------------
__global__ __launch_bounds__(256)
void norm_weights(float* __restrict__ Wt)
{
    const size_t row = blockIdx.x;
    const float inv = g_inv[row];
    float4* p = (float4*)(Wt + row*(size_t)Sz);
    float4 a = p[threadIdx.x];
    float4 b = p[threadIdx.x + 256];
    a.x*=inv; a.y*=inv; a.z*=inv; a.w*=inv;
    b.x*=inv; b.y*=inv; b.z*=inv; b.w*=inv;
    p[threadIdx.x] = a;
    p[threadIdx.x + 256] = b;
}

// ---------------- dense: out = attn @ W^T + b ------------------------------
__global__ __launch_bounds__(256)
void dense_tc(const float* __restrict__ Wm, const float* __restrict__ bias,
              float* __restrict__ C)
{
    extern __shared__ uint32_t sm[];
    __shared__ float bias_s[128];
    const int tid = threadIdx.x;
    const int bn = blockIdx.x*128, bm = blockIdx.y*128;
    if (tid < 128) bias_s[tid] = bias[bn + tid];

    float acc[4][4][4]; ZERO_ACC(acc, 4);
    gemm_bf16<128>(g_attn + (size_t)bm*Dz, Dz, Wm + (size_t)bn*Dz, Dz, Dz, sm, acc, tid);

    float* stg = (float*)sm;
    stage_acc<128>(stg, acc, tid, 1.f, bias_s);
    __syncthreads();

    for (int i=0;i<16;i++){
        int f = i*256 + tid, r = f>>5, c4 = f&31;
        float4 v = *(float4*)&stg[(size_t)r*132 + c4*4];
        *(float4*)&C[(size_t)(bm + r)*Dz + bn + c4*4] = v;
    }
}

// ---------------------------------------------------------------------------
#define SMEM_128 81920

extern "C" void kernel_launch(void* const* d_in, const int* in_sizes, int n_in,
                              void* d_out, int out_size)
{
    const float* q    = (const float*)d_in[0];
    const float* k    = (const float*)d_in[1];
    const float* v    = (const float*)d_in[2];
    const int*   mask = (const int*)  d_in[3];
    const float* wq_w = (const float*)d_in[4];
    const float* wq_b = (const float*)d_in[5];
    const float* wk_w = (const float*)d_in[6];
    const float* wk_b = (const float*)d_in[7];
    const float* wv_w = (const float*)d_in[8];
    const float* wv_b = (const float*)d_in[9];
    const float* dw   = (const float*)d_in[10];
    const float* db   = (const float*)d_in[11];

    float* out     = (float*)d_out;                 // [B,S,D]
    float* weights = out + (size_t)Bz * Sz * Dz;    // [B,H,S,S]

    static int configured = 0;
    if (!configured){
        cudaFuncSetAttribute(proj_tc,    cudaFuncAttributeMaxDynamicSharedMemorySize, SMEM_128);
        cudaFuncSetAttribute(attn_fused, cudaFuncAttributeMaxDynamicSharedMemorySize, F_SMEM_BYTES);
        cudaFuncSetAttribute(dense_tc,   cudaFuncAttributeMaxDynamicSharedMemorySize, SMEM_128);
        configured = 1;
    }

    dim3 gProj(Dz/128, NROW/128, 3);          // (8, 32, 3)
    proj_tc<<<gProj, 256, SMEM_128>>>(q, k, v, wq_w, wq_b, wk_w, wk_b, wv_w, wv_b);

    dim3 gF(Sz/128, Bz*Hz);                   // (16, 32)
    attn_fused<<<gF, 256, F_SMEM_BYTES>>>(mask, weights);

    norm_weights<<<Bz*Hz*Sz, 256>>>(weights);

    dim3 gDn(Dz/128, NROW/128);               // (8, 32)
    dense_tc<<<gDn, 256, SMEM_128>>>(dw, db, out);
}